// round 1
// baseline (speedup 1.0000x reference)
#include <cuda_runtime.h>
#include <cstdint>

#define T   2048
#define E   256
#define H2  256
#define G4  1024    // 4*H2
#define L   32
#define CLS 0
#define SEP 31
#define NEGV (-10000.0f)

// ---------------- scratch (static device globals; no allocations) ----------
__device__ float g_xproj[2][T][G4];   // input projections + bias, per direction
__device__ float g_hs[T][2 * H2];     // [fwd h | bwd h] per timestep
__device__ float g_logits[T][L];      // emissions

// ===========================================================================
// K1: embedding gather + input projection GEMM (both directions)
// out[dir][t][j] = b[j] + sum_e emb[ids[t]][e] * W_ih[j][e]
// Tiles: 64 t x 64 j, BK=16, 256 threads, 4x4 microtile.
// ===========================================================================
__global__ __launch_bounds__(256) void k_proj(
    const int* __restrict__ ids, const float* __restrict__ emb,
    const float* __restrict__ w_f, const float* __restrict__ b_f,
    const float* __restrict__ w_b, const float* __restrict__ b_b)
{
    const int dir = blockIdx.z;
    const float* W = dir ? w_b : w_f;
    const float* B = dir ? b_b : b_f;
    const int t0 = blockIdx.y * 64;
    const int j0 = blockIdx.x * 64;

    __shared__ float Xs[16][65];
    __shared__ float Ws[16][65];
    __shared__ int   ids_s[64];

    const int tid = threadIdx.x;
    if (tid < 64) ids_s[tid] = ids[t0 + tid];
    __syncthreads();

    const int tx = tid & 15;   // j quad
    const int ty = tid >> 4;   // t quad

    float acc[4][4];
#pragma unroll
    for (int jq = 0; jq < 4; ++jq) {
        float bv = B[j0 + tx * 4 + jq];
#pragma unroll
        for (int iq = 0; iq < 4; ++iq) acc[iq][jq] = bv;
    }

    const int kk    = tid & 15;
    const int rbase = tid >> 4;

    for (int k0 = 0; k0 < E; k0 += 16) {
#pragma unroll
        for (int p = 0; p < 4; ++p) {
            int row = rbase + p * 16;
            Xs[kk][row] = emb[(size_t)ids_s[row] * E + k0 + kk];
            Ws[kk][row] = W[(size_t)(j0 + row) * E + k0 + kk];
        }
        __syncthreads();
#pragma unroll
        for (int k = 0; k < 16; ++k) {
            float a[4], b[4];
#pragma unroll
            for (int iq = 0; iq < 4; ++iq) a[iq] = Xs[k][ty * 4 + iq];
#pragma unroll
            for (int jq = 0; jq < 4; ++jq) b[jq] = Ws[k][tx * 4 + jq];
#pragma unroll
            for (int iq = 0; iq < 4; ++iq)
#pragma unroll
                for (int jq = 0; jq < 4; ++jq)
                    acc[iq][jq] += a[iq] * b[jq];
        }
        __syncthreads();
    }

#pragma unroll
    for (int iq = 0; iq < 4; ++iq) {
        int t = t0 + ty * 4 + iq;
#pragma unroll
        for (int jq = 0; jq < 4; ++jq)
            g_xproj[dir][t][j0 + tx * 4 + jq] = acc[iq][jq];
    }
}

// ===========================================================================
// K2: BiLSTM recurrence. 2 clusters (fwd/bwd) x 8 CTAs x 512 threads.
// Each CTA owns 32 h-outputs -> 128 z-rows; W_hh rows live in registers
// (64 floats/thread, 4 threads per z-row). h broadcast across the cluster
// via st.shared::cluster; one cluster barrier per timestep.
// ===========================================================================
__global__ void __cluster_dims__(8, 1, 1) __launch_bounds__(512, 1)
k_lstm(const float* __restrict__ whh_f, const float* __restrict__ whh_b,
       const float* __restrict__ h0,    const float* __restrict__ c0)
{
    const int tid = threadIdx.x;
    unsigned rank, cid;
    asm("mov.u32 %0, %%cluster_ctarank;" : "=r"(rank));
    asm("mov.u32 %0, %%clusterid.x;"     : "=r"(cid));
    const int dir = (int)cid;      // 0 = fwd, 1 = bwd
    const int r   = (int)rank;     // 0..7

    const float* W = dir ? whh_b : whh_f;

    const int row_local = tid >> 2;        // 0..127
    const int seg       = tid & 3;         // 64-wide chunk of h
    const int gate      = row_local >> 5;  // 0:i 1:f 2:g 3:o
    const int jj        = row_local & 31;
    const int grow      = gate * H2 + r * 32 + jj;   // global z row

    // persistent weights in registers: 16 float4 = 64 floats
    float4 w[16];
    {
        const float4* wr =
            reinterpret_cast<const float4*>(W + (size_t)grow * H2 + seg * 64);
#pragma unroll
        for (int i = 0; i < 16; ++i) w[i] = wr[i];
    }

    __shared__ __align__(16) float hbuf[2][H2];
    __shared__ float zbuf[128];

    if (tid < H2) hbuf[0][tid] = h0[dir * H2 + tid];
    float c = 0.f;
    if (tid < 32) c = c0[dir * H2 + r * 32 + tid];
    __syncthreads();

    const float* xp = &g_xproj[dir][0][0];
    float xpv = 0.f;
    if (seg == 0) {
        int t0i = dir ? (T - 1) : 0;
        xpv = xp[(size_t)t0i * G4 + grow];
    }

    for (int step = 0; step < T; ++step) {
        const int par = step & 1;
        const int tt  = dir ? (T - 1 - step) : step;

        // z_partial = dot(w_seg, h_seg)
        const float4* h4 =
            reinterpret_cast<const float4*>(&hbuf[par][seg * 64]);
        float s0 = 0.f, s1 = 0.f, s2 = 0.f, s3 = 0.f;
#pragma unroll
        for (int i = 0; i < 16; i += 4) {
            float4 a0 = h4[i], a1 = h4[i + 1], a2 = h4[i + 2], a3 = h4[i + 3];
            s0 += w[i    ].x * a0.x + w[i    ].y * a0.y + w[i    ].z * a0.z + w[i    ].w * a0.w;
            s1 += w[i + 1].x * a1.x + w[i + 1].y * a1.y + w[i + 1].z * a1.z + w[i + 1].w * a1.w;
            s2 += w[i + 2].x * a2.x + w[i + 2].y * a2.y + w[i + 2].z * a2.z + w[i + 2].w * a2.w;
            s3 += w[i + 3].x * a3.x + w[i + 3].y * a3.y + w[i + 3].z * a3.z + w[i + 3].w * a3.w;
        }
        float s = (s0 + s1) + (s2 + s3);
        s += __shfl_xor_sync(0xffffffffu, s, 1);
        s += __shfl_xor_sync(0xffffffffu, s, 2);
        if (seg == 0) zbuf[row_local] = s + xpv;
        __syncthreads();

        if (tid < 32) {
            float zi = zbuf[tid], zf = zbuf[32 + tid];
            float zg = zbuf[64 + tid], zo = zbuf[96 + tid];
            float ig = 1.f / (1.f + __expf(-zi));
            float fg = 1.f / (1.f + __expf(-zf));
            float gg = tanhf(zg);
            float og = 1.f / (1.f + __expf(-zo));
            c = fg * c + ig * gg;
            float h = og * tanhf(c);

            const int np = par ^ 1;
            uint32_t laddr = (uint32_t)__cvta_generic_to_shared(
                &hbuf[np][r * 32 + tid]);
#pragma unroll
            for (int p = 0; p < 8; ++p) {
                uint32_t raddr;
                asm volatile("mapa.shared::cluster.u32 %0, %1, %2;"
                             : "=r"(raddr) : "r"(laddr), "r"(p));
                asm volatile("st.shared::cluster.f32 [%0], %1;"
                             :: "r"(raddr), "f"(h) : "memory");
            }
            g_hs[tt][dir * H2 + r * 32 + tid] = h;
        }

        // prefetch next timestep's input projection (hidden under barrier)
        if (seg == 0 && step + 1 < T) {
            int tn = dir ? (T - 2 - step) : (step + 1);
            xpv = xp[(size_t)tn * G4 + grow];
        }

        asm volatile("barrier.cluster.arrive.aligned;" ::: "memory");
        asm volatile("barrier.cluster.wait.aligned;"   ::: "memory");
    }
}

// ===========================================================================
// K3: logits[t][l] = b_lin[l] + dot(hs[t], w_lin[l])  (512-wide dots)
// warp per timestep; 64 blocks x 32 warps.
// ===========================================================================
__global__ __launch_bounds__(1024) void k_linear(
    const float* __restrict__ wlin, const float* __restrict__ blin)
{
    const int warp = threadIdx.x >> 5;
    const int lane = threadIdx.x & 31;
    const int t = blockIdx.x * 32 + warp;

    const float4* h4 = reinterpret_cast<const float4*>(&g_hs[t][0]);
    float4 hv[4];
#pragma unroll
    for (int i = 0; i < 4; ++i) hv[i] = h4[lane + 32 * i];

    for (int l = 0; l < L; ++l) {
        const float4* w4 =
            reinterpret_cast<const float4*>(wlin + (size_t)l * 2 * H2);
        float s = 0.f;
#pragma unroll
        for (int i = 0; i < 4; ++i) {
            float4 wv = w4[lane + 32 * i];
            s += wv.x * hv[i].x + wv.y * hv[i].y + wv.z * hv[i].z + wv.w * hv[i].w;
        }
#pragma unroll
        for (int o = 16; o; o >>= 1) s += __shfl_xor_sync(0xffffffffu, s, o);
        if (lane == 0) g_logits[t][l] = s + blin[l];
    }
}

// ===========================================================================
// K4: CRF forward algorithm + gold path score. One block, 32 warps.
// Warp n owns next-tag n; trans[n][lane] in a register. Renormalization
// offset = max(alpha[0], alpha[1]) from previous step -> no max-reduce in
// the serial chain (alpha spread is bounded by trans/emit ranges).
// ===========================================================================
__global__ __launch_bounds__(1024, 1) void k_crf(
    const float* __restrict__ trans, const int* __restrict__ target,
    float* __restrict__ out)
{
    const int tid  = threadIdx.x;
    const int warp = tid >> 5;
    const int lane = tid & 31;

    __shared__ float tr_s[L * L];
    __shared__ float al[2][L];
    __shared__ float red[32];
    __shared__ float gold_s;

    float tr = trans[warp * L + lane];
    tr_s[warp * L + lane] = tr;
    __syncthreads();

    // ---- gold path score (parallel over t) ----
    float g = 0.f;
    for (int t = tid; t < T; t += 1024) {
        int cur  = target[t];
        int prev = (t == 0) ? CLS : target[t - 1];
        g += tr_s[cur * L + prev] + g_logits[t][cur];
    }
    if (tid == 0) g += tr_s[SEP * L + target[T - 1]];
#pragma unroll
    for (int o = 16; o; o >>= 1) g += __shfl_xor_sync(0xffffffffu, g, o);
    if (lane == 0) red[warp] = g;
    __syncthreads();
    if (warp == 0) {
        float v = red[lane];
#pragma unroll
        for (int o = 16; o; o >>= 1) v += __shfl_xor_sync(0xffffffffu, v, o);
        if (lane == 0) gold_s = v;
        // init alpha
        al[0][lane] = (lane == CLS) ? 0.f : NEGV;
    }
    __syncthreads();

    // ---- forward recursion ----
    float emit_next = g_logits[0][warp];
    for (int t = 0; t < T; ++t) {
        const int par = t & 1;
        float emit = emit_next;
        if (t + 1 < T) emit_next = g_logits[t + 1][warp];

        float a   = al[par][lane];
        float off = fmaxf(al[par][0], al[par][1]);
        float e   = __expf(a - off + tr);
#pragma unroll
        for (int o = 16; o; o >>= 1) e += __shfl_xor_sync(0xffffffffu, e, o);
        float anew = __logf(e) + off + emit;
        if (lane == 0) al[par ^ 1][warp] = anew;
        __syncthreads();
    }

    // ---- termination: forward = lse(alpha + trans[SEP]); out = fwd - gold
    if (warp == SEP) {
        const int fp = T & 1;   // T even -> alpha in al[0]
        float a   = al[fp][lane];
        float off = fmaxf(al[fp][0], al[fp][1]);
        float e   = __expf(a - off + tr);  // tr = trans[SEP][lane]
#pragma unroll
        for (int o = 16; o; o >>= 1) e += __shfl_xor_sync(0xffffffffu, e, o);
        if (lane == 0) out[0] = __logf(e) + off - gold_s;
    }
}

// ===========================================================================
extern "C" void kernel_launch(void* const* d_in, const int* in_sizes, int n_in,
                              void* d_out, int out_size)
{
    const int*   ids    = (const int*)d_in[0];
    // d_in[1] attention_mask: all ones, unused by reference
    const int*   target = (const int*)d_in[2];
    const float* emb    = (const float*)d_in[3];
    const float* w_ih_f = (const float*)d_in[4];
    const float* w_hh_f = (const float*)d_in[5];
    const float* b_f    = (const float*)d_in[6];
    const float* w_ih_b = (const float*)d_in[7];
    const float* w_hh_b = (const float*)d_in[8];
    const float* b_b    = (const float*)d_in[9];
    const float* w_lin  = (const float*)d_in[10];
    const float* b_lin  = (const float*)d_in[11];
    const float* trans  = (const float*)d_in[12];
    const float* h0     = (const float*)d_in[13];
    const float* c0     = (const float*)d_in[14];
    float* out = (float*)d_out;

    dim3 g1(G4 / 64, T / 64, 2);
    k_proj<<<g1, 256>>>(ids, emb, w_ih_f, b_f, w_ih_b, b_b);
    k_lstm<<<16, 512>>>(w_hh_f, w_hh_b, h0, c0);
    k_linear<<<T / 32, 1024>>>(w_lin, b_lin);
    k_crf<<<1, 1024>>>(trans, target, out);
}

// round 2
// speedup vs baseline: 4.1180x; 4.1180x over previous
#include <cuda_runtime.h>
#include <cstdint>

#define T   2048
#define E   256
#define H2  256
#define G4  1024    // 4*H2
#define L   32
#define CLS 0
#define SEP 31
#define NEGV (-10000.0f)

// ---------------- scratch (static device globals; no allocations) ----------
__device__ float g_xproj[2][T][G4];   // input projections + bias, per direction
__device__ float g_hs[T][2 * H2];     // [fwd h | bwd h] per timestep
__device__ float g_logits[T][L];      // emissions (log domain, for gold score)
__device__ float g_pemit[T][L];       // exp(emissions) for exp-domain CRF

// ---------------- small PTX helpers ----------------------------------------
__device__ __forceinline__ uint32_t sh32(const void* p) {
    return (uint32_t)__cvta_generic_to_shared(p);
}
__device__ __forceinline__ uint32_t mapa_sh(uint32_t laddr, uint32_t rank) {
    uint32_t r;
    asm("mapa.shared::cluster.u32 %0, %1, %2;" : "=r"(r) : "r"(laddr), "r"(rank));
    return r;
}
__device__ __forceinline__ void mbar_init(uint32_t a, uint32_t cnt) {
    asm volatile("mbarrier.init.shared.b64 [%0], %1;" :: "r"(a), "r"(cnt) : "memory");
}
__device__ __forceinline__ void mbar_expect_tx(uint32_t a, uint32_t bytes) {
    asm volatile("mbarrier.arrive.expect_tx.shared.b64 _, [%0], %1;"
                 :: "r"(a), "r"(bytes) : "memory");
}
__device__ __forceinline__ void mbar_wait(uint32_t a, uint32_t phase) {
    uint32_t done;
    asm volatile(
        "{\n\t.reg .pred p;\n\t"
        "mbarrier.try_wait.parity.acquire.cluster.shared::cta.b64 p, [%1], %2;\n\t"
        "selp.b32 %0, 1, 0, p;\n\t}"
        : "=r"(done) : "r"(a), "r"(phase) : "memory");
    if (!done) {
        asm volatile(
            "{\n\t.reg .pred P1;\n"
            "W_%=:\n\t"
            "mbarrier.try_wait.parity.acquire.cluster.shared::cta.b64 P1, [%0], %1, 0x989680;\n\t"
            "@P1 bra.uni D_%=;\n\t"
            "bra.uni W_%=;\n"
            "D_%=:\n\t}"
            :: "r"(a), "r"(phase) : "memory");
    }
}
__device__ __forceinline__ void st_async_f32(uint32_t raddr, float v, uint32_t rmbar) {
    asm volatile(
        "st.async.shared::cluster.mbarrier::complete_tx::bytes.b32 [%0], %1, [%2];"
        :: "r"(raddr), "r"(__float_as_uint(v)), "r"(rmbar) : "memory");
}
__device__ __forceinline__ void fma2(unsigned long long& d,
                                     unsigned long long a, unsigned long long b) {
    asm("fma.rn.f32x2 %0, %1, %2, %0;" : "+l"(d) : "l"(a), "l"(b));
}
__device__ __forceinline__ void unpk(float& lo, float& hi, unsigned long long v) {
    asm("mov.b64 {%0, %1}, %2;" : "=f"(lo), "=f"(hi) : "l"(v));
}
__device__ __forceinline__ float tanhfast(float x) {
    float y;
    asm("tanh.approx.f32 %0, %1;" : "=f"(y) : "f"(x));
    return y;
}

// ===========================================================================
// K1: embedding gather + input projection GEMM (both directions)
// ===========================================================================
__global__ __launch_bounds__(256) void k_proj(
    const int* __restrict__ ids, const float* __restrict__ emb,
    const float* __restrict__ w_f, const float* __restrict__ b_f,
    const float* __restrict__ w_b, const float* __restrict__ b_b)
{
    const int dir = blockIdx.z;
    const float* W = dir ? w_b : w_f;
    const float* B = dir ? b_b : b_f;
    const int t0 = blockIdx.y * 64;
    const int j0 = blockIdx.x * 64;

    __shared__ float Xs[16][65];
    __shared__ float Ws[16][65];
    __shared__ int   ids_s[64];

    const int tid = threadIdx.x;
    if (tid < 64) ids_s[tid] = ids[t0 + tid];
    __syncthreads();

    const int tx = tid & 15;
    const int ty = tid >> 4;

    float acc[4][4];
#pragma unroll
    for (int jq = 0; jq < 4; ++jq) {
        float bv = B[j0 + tx * 4 + jq];
#pragma unroll
        for (int iq = 0; iq < 4; ++iq) acc[iq][jq] = bv;
    }

    const int kk    = tid & 15;
    const int rbase = tid >> 4;

    for (int k0 = 0; k0 < E; k0 += 16) {
#pragma unroll
        for (int p = 0; p < 4; ++p) {
            int row = rbase + p * 16;
            Xs[kk][row] = emb[(size_t)ids_s[row] * E + k0 + kk];
            Ws[kk][row] = W[(size_t)(j0 + row) * E + k0 + kk];
        }
        __syncthreads();
#pragma unroll
        for (int k = 0; k < 16; ++k) {
            float a[4], b[4];
#pragma unroll
            for (int iq = 0; iq < 4; ++iq) a[iq] = Xs[k][ty * 4 + iq];
#pragma unroll
            for (int jq = 0; jq < 4; ++jq) b[jq] = Ws[k][tx * 4 + jq];
#pragma unroll
            for (int iq = 0; iq < 4; ++iq)
#pragma unroll
                for (int jq = 0; jq < 4; ++jq)
                    acc[iq][jq] += a[iq] * b[jq];
        }
        __syncthreads();
    }

#pragma unroll
    for (int iq = 0; iq < 4; ++iq) {
        int t = t0 + ty * 4 + iq;
#pragma unroll
        for (int jq = 0; jq < 4; ++jq)
            g_xproj[dir][t][j0 + tx * 4 + jq] = acc[iq][jq];
    }
}

// ===========================================================================
// K2: BiLSTM recurrence. 2 clusters (fwd/bwd) x 8 CTAs x 256 threads.
// - f32x2 packed FMA (2x FFMA rate), weights in registers (128 f/thread)
// - k-interleaved seg partition: seg in {0,1}, thread's float4 chunks are
//   j = seg + 2m -> warp touches 2 disjoint bank groups, 16-way broadcast
// - cross-CTA h exchange via st.async + mbarrier expect_tx (no barrier.cluster)
// - double-buffered h AND z; single __syncthreads per step
// ===========================================================================
__global__ void __cluster_dims__(8, 1, 1) __launch_bounds__(256, 1)
k_lstm(const float* __restrict__ whh_f, const float* __restrict__ whh_b,
       const float* __restrict__ h0,    const float* __restrict__ c0)
{
    const int tid = threadIdx.x;
    unsigned rank, cid;
    asm("mov.u32 %0, %%cluster_ctarank;" : "=r"(rank));
    asm("mov.u32 %0, %%clusterid.x;"     : "=r"(cid));
    const int dir = (int)cid;
    const int r   = (int)rank;

    const float* W = dir ? whh_b : whh_f;

    const int seg  = tid & 1;
    const int row  = tid >> 1;          // 0..127 local z-row
    const int gate = row >> 5;
    const int jj   = row & 31;
    const int grow = gate * H2 + r * 32 + jj;   // global z-row
    const int v    = tid & 31;          // activation value index
    const int p    = tid >> 5;          // peer CTA for the h broadcast

    // weights pre-packed as f32x2 pairs: 32 ulonglong2 = 128 floats
    ulonglong2 w2[32];
    {
        const ulonglong2* wr =
            reinterpret_cast<const ulonglong2*>(W + (size_t)grow * H2);
#pragma unroll
        for (int m = 0; m < 32; ++m) w2[m] = wr[seg + 2 * m];
    }

    __shared__ __align__(16) float hbuf[2][H2];
    __shared__ float zbuf[2][128];
    __shared__ __align__(8) unsigned long long mbar[2];

    if (tid == 0) { mbar_init(sh32(&mbar[0]), 1); mbar_init(sh32(&mbar[1]), 1); }
    if (tid < H2) hbuf[0][tid] = h0[dir * H2 + tid];
    float c = c0[dir * H2 + r * 32 + v];
    __syncthreads();
    asm volatile("barrier.cluster.arrive.aligned;" ::: "memory");
    asm volatile("barrier.cluster.wait.aligned;"   ::: "memory");

    // precomputed remote addresses (peer p): data slot + mbarrier, per buffer
    const uint32_t dst0 = mapa_sh(sh32(&hbuf[0][r * 32 + v]), (uint32_t)p);
    const uint32_t dst1 = mapa_sh(sh32(&hbuf[1][r * 32 + v]), (uint32_t)p);
    const uint32_t rmb0 = mapa_sh(sh32(&mbar[0]), (uint32_t)p);
    const uint32_t rmb1 = mapa_sh(sh32(&mbar[1]), (uint32_t)p);
    const uint32_t lmb0 = sh32(&mbar[0]);
    const uint32_t lmb1 = sh32(&mbar[1]);

    const float* xp = &g_xproj[dir][0][0];
    float xpv = 0.f;
    if (seg == 0) {
        int t0i = dir ? (T - 1) : 0;
        xpv = xp[(size_t)t0i * G4 + grow];
    }

    for (int s = 0; s < T; ++s) {
        const int cb = s & 1;
        const int tt = dir ? (T - 1 - s) : s;

        // announce this step's exchange (exchange s on mbar[cb])
        if (tid == 0 && s < T - 1)
            mbar_expect_tx(cb ? lmb1 : lmb0, 8 * H2 * 4 / 8); // 1024 bytes
        // wait for exchange s-1 (mbar[(s-1)&1]) delivering hbuf[cb]
        if (s > 0)
            mbar_wait(cb ? lmb0 : lmb1, (uint32_t)(((s - 1) >> 1) & 1));

        // ---- dot: z[row] = W_hh[grow] . h  (seg-split, f32x2) ----
        const ulonglong2* h2 =
            reinterpret_cast<const ulonglong2*>(&hbuf[cb][0]);
        unsigned long long a0 = 0, a1 = 0, a2 = 0, a3 = 0;
#pragma unroll
        for (int m = 0; m < 32; m += 2) {
            ulonglong2 hv0 = h2[seg + 2 * m];
            ulonglong2 hv1 = h2[seg + 2 * m + 2];
            fma2(a0, w2[m].x,     hv0.x);
            fma2(a1, w2[m].y,     hv0.y);
            fma2(a2, w2[m + 1].x, hv1.x);
            fma2(a3, w2[m + 1].y, hv1.y);
        }
        float l0, h0f, l1, h1f, l2, h2f, l3, h3f;
        unpk(l0, h0f, a0); unpk(l1, h1f, a1);
        unpk(l2, h2f, a2); unpk(l3, h3f, a3);
        float sd = ((l0 + h0f) + (l1 + h1f)) + ((l2 + h2f) + (l3 + h3f));
        sd += __shfl_xor_sync(0xffffffffu, sd, 1);
        if (seg == 0) zbuf[cb][row] = sd + xpv;
        __syncthreads();

        // prefetch next timestep's input projection
        if (seg == 0 && s + 1 < T) {
            int tn = dir ? (T - 2 - s) : (s + 1);
            xpv = xp[(size_t)tn * G4 + grow];
        }

        // ---- activation (all 256 threads, 8 redundant groups of 32) ----
        float zi = zbuf[cb][v],      zf = zbuf[cb][32 + v];
        float zg = zbuf[cb][64 + v], zo = zbuf[cb][96 + v];
        float ig = 0.5f + 0.5f * tanhfast(0.5f * zi);
        float fg = 0.5f + 0.5f * tanhfast(0.5f * zf);
        float gg = tanhfast(zg);
        float og = 0.5f + 0.5f * tanhfast(0.5f * zo);
        c = fg * c + ig * gg;
        float h = og * tanhfast(c);

        // broadcast: thread sends value v to peer p (incl. self) into hbuf[cb^1]
        if (s < T - 1)
            st_async_f32(cb ? dst0 : dst1, h, cb ? rmb1 : rmb0);
        if (p == 0)
            g_hs[tt][dir * H2 + r * 32 + v] = h;
    }
}

// ===========================================================================
// K3: logits[t][l] = b_lin[l] + dot(hs[t], w_lin[l]); also exp(logits)
// ===========================================================================
__global__ __launch_bounds__(1024) void k_linear(
    const float* __restrict__ wlin, const float* __restrict__ blin)
{
    const int warp = threadIdx.x >> 5;
    const int lane = threadIdx.x & 31;
    const int t = blockIdx.x * 32 + warp;

    const float4* h4 = reinterpret_cast<const float4*>(&g_hs[t][0]);
    float4 hv[4];
#pragma unroll
    for (int i = 0; i < 4; ++i) hv[i] = h4[lane + 32 * i];

    for (int l = 0; l < L; ++l) {
        const float4* w4 =
            reinterpret_cast<const float4*>(wlin + (size_t)l * 2 * H2);
        float s = 0.f;
#pragma unroll
        for (int i = 0; i < 4; ++i) {
            float4 wv = w4[lane + 32 * i];
            s += wv.x * hv[i].x + wv.y * hv[i].y + wv.z * hv[i].z + wv.w * hv[i].w;
        }
#pragma unroll
        for (int o = 16; o; o >>= 1) s += __shfl_xor_sync(0xffffffffu, s, o);
        if (lane == 0) {
            float lg = s + blin[l];
            g_logits[t][l] = lg;
            g_pemit[t][l]  = expf(lg);
        }
    }
}

// ===========================================================================
// K4: CRF. Gold score in parallel (all 32 warps), then the forward recursion
// in exp-domain inside ONE warp: e' = (exp(trans) . e) * exp(emit), with
// per-step renormalization by exponent-bit extraction (no exp/log in loop).
// ===========================================================================
__global__ __launch_bounds__(1024, 1) void k_crf(
    const float* __restrict__ trans, const int* __restrict__ target,
    float* __restrict__ out)
{
    const int tid  = threadIdx.x;
    const int warp = tid >> 5;
    const int lane = tid & 31;

    __shared__ float tr_s[L * L];
    __shared__ float red[32];
    __shared__ float gold_s;

    tr_s[tid] = trans[tid];
    __syncthreads();

    // ---- gold path score (parallel over t) ----
    float g = 0.f;
    for (int t = tid; t < T; t += 1024) {
        int cur  = target[t];
        int prev = (t == 0) ? CLS : target[t - 1];
        g += tr_s[cur * L + prev] + g_logits[t][cur];
    }
    if (tid == 0) g += tr_s[SEP * L + target[T - 1]];
#pragma unroll
    for (int o = 16; o; o >>= 1) g += __shfl_xor_sync(0xffffffffu, g, o);
    if (lane == 0) red[warp] = g;
    __syncthreads();
    if (tid == 0) {
        float vv = 0.f;
        for (int i = 0; i < 32; ++i) vv += red[i];
        gold_s = vv;
    }
    __syncthreads();

    if (warp == 0) {
        // lane n owns next-tag n; Mrow[p] = exp(trans[n][p])
        float Mrow[32];
#pragma unroll
        for (int p2 = 0; p2 < 32; ++p2) Mrow[p2] = expf(tr_s[lane * L + p2]);
        float Mt = expf(tr_s[SEP * L + lane]);

        float e = (lane == CLS) ? 1.f : 0.f;
        int ksum = 0;

        float pe[4];
#pragma unroll
        for (int i = 0; i < 4; ++i) pe[i] = g_pemit[i][lane];

        for (int t = 0; t < T; t += 4) {
#pragma unroll
            for (int q = 0; q < 4; ++q) {
                float b0 = 0.f, b1 = 0.f, b2 = 0.f, b3 = 0.f;
#pragma unroll
                for (int p2 = 0; p2 < 32; p2 += 4) {
                    b0 += Mrow[p2]     * __shfl_sync(0xffffffffu, e, p2);
                    b1 += Mrow[p2 + 1] * __shfl_sync(0xffffffffu, e, p2 + 1);
                    b2 += Mrow[p2 + 2] * __shfl_sync(0xffffffffu, e, p2 + 2);
                    b3 += Mrow[p2 + 3] * __shfl_sync(0xffffffffu, e, p2 + 3);
                }
                float acc = (b0 + b1) + (b2 + b3);
                // renormalize by 2^-k where k = exponent of lane-1's acc
                float ref = __shfl_sync(0xffffffffu, acc, 1);
                unsigned eb = (__float_as_uint(ref) >> 23) & 255u;
                float scale = __uint_as_float((254u - eb) << 23);
                ksum += (int)eb - 127;
                e = acc * scale * pe[q];
                int tn = t + 4 + q;
                pe[q] = (tn < T) ? g_pemit[tn][lane] : 0.f;
            }
        }

        // termination: fwd = log(sum_n e[n]*Mt[n]) + ksum*ln2
        float s2 = e * Mt;
#pragma unroll
        for (int o = 16; o; o >>= 1) s2 += __shfl_xor_sync(0xffffffffu, s2, o);
        if (lane == 0)
            out[0] = logf(s2) + (float)ksum * 0.693147180559945f - gold_s;
    }
}

// ===========================================================================
extern "C" void kernel_launch(void* const* d_in, const int* in_sizes, int n_in,
                              void* d_out, int out_size)
{
    const int*   ids    = (const int*)d_in[0];
    const int*   target = (const int*)d_in[2];
    const float* emb    = (const float*)d_in[3];
    const float* w_ih_f = (const float*)d_in[4];
    const float* w_hh_f = (const float*)d_in[5];
    const float* b_f    = (const float*)d_in[6];
    const float* w_ih_b = (const float*)d_in[7];
    const float* w_hh_b = (const float*)d_in[8];
    const float* b_b    = (const float*)d_in[9];
    const float* w_lin  = (const float*)d_in[10];
    const float* b_lin  = (const float*)d_in[11];
    const float* trans  = (const float*)d_in[12];
    const float* h0     = (const float*)d_in[13];
    const float* c0     = (const float*)d_in[14];
    float* out = (float*)d_out;

    dim3 g1(G4 / 64, T / 64, 2);
    k_proj<<<g1, 256>>>(ids, emb, w_ih_f, b_f, w_ih_b, b_b);
    k_lstm<<<16, 256>>>(w_hh_f, w_hh_b, h0, c0);
    k_linear<<<T / 32, 1024>>>(w_lin, b_lin);
    k_crf<<<1, 1024>>>(trans, target, out);
}